// round 6
// baseline (speedup 1.0000x reference)
#include <cuda_runtime.h>
#include <cstdint>

// Scratch for the input-projection result: pre[row=b*512+t][32] (g*8+n)
// 512*512*32 floats = 33.5 MB. __device__ global (no allocation allowed).
__device__ float g_pre[512 * 512 * 32];

// ---------------------------------------------------------------------------
// Packed fp32x2 FMA (Blackwell): two fp32 FMAs per issue slot, full precision.
// ---------------------------------------------------------------------------
__device__ __forceinline__ unsigned long long ffma2(unsigned long long a,
                                                    unsigned long long b,
                                                    unsigned long long c) {
    unsigned long long d;
    asm("fma.rn.f32x2 %0, %1, %2, %3;" : "=l"(d) : "l"(a), "l"(b), "l"(c));
    return d;
}

// ---------------------------------------------------------------------------
// Kernel 1: pre[r][c] = sum_k X[r][k] * W[c][k] + bias[c] + theta[c]
//   M = 262144 rows, K = 256, N = 32 cols (col c = gate*8 + qubit)
//   Block: 256 threads, 128 rows, all 32 cols. f32x2 packed over row pairs.
// ---------------------------------------------------------------------------
constexpr int KTILE = 32;
constexpr int RPB   = 128;   // rows per block
constexpr int XS    = 130;   // padded smem row stride (floats)

__global__ void __launch_bounds__(256, 2) gemm_kernel(
    const float* __restrict__ X,
    const float* __restrict__ Wf, const float* __restrict__ bf,
    const float* __restrict__ Wi, const float* __restrict__ bi,
    const float* __restrict__ Wg, const float* __restrict__ bg,
    const float* __restrict__ Wo, const float* __restrict__ bo,
    const float* __restrict__ th)
{
    extern __shared__ float sm[];
    float2* sW2 = reinterpret_cast<float2*>(sm);   // [256][32] duplicated pairs (64 KB)
    float*  sX  = sm + 16384;                      // [2][KTILE][XS] (33.3 KB)

    const int tid = threadIdx.x;

    // Stage W as duplicated (w,w) pairs. W rows have stride 264 (last 8 cols are
    // the recurrent part, handled in kernel 2).
    {
        const float* Wp[4] = {Wf, Wi, Wg, Wo};
        for (int idx = tid; idx < 8192; idx += 256) {
            int k = idx >> 5, c = idx & 31;
            float w = Wp[c >> 3][(c & 7) * 264 + k];
            sW2[k * 32 + c] = make_float2(w, w);
        }
    }

    const size_t row0 = (size_t)blockIdx.x * RPB;
    const int rp = tid & 63;   // row pair 0..63 -> rows 2*rp, 2*rp+1
    const int cg = tid >> 6;   // gate / col group 0..3 -> cols cg*8 .. cg*8+7

    int r_[4], k4_[4];
#pragma unroll
    for (int i = 0; i < 4; i++) {
        int f = tid + i * 256;
        r_[i]  = f >> 3;
        k4_[i] = f & 7;
    }

    float4 ldv[4];
#pragma unroll
    for (int i = 0; i < 4; i++)
        ldv[i] = *reinterpret_cast<const float4*>(X + (row0 + r_[i]) * 256 + k4_[i] * 4);

    unsigned long long acc[8];
#pragma unroll
    for (int c = 0; c < 8; c++) acc[c] = 0ull;

    // store tile 0 (buffer 0); first __syncthreads also covers sW2.
    {
        float* dstb = sX;
#pragma unroll
        for (int i = 0; i < 4; i++) {
            float* dst = dstb + k4_[i] * 4 * XS + r_[i];
            dst[0 * XS] = ldv[i].x; dst[1 * XS] = ldv[i].y;
            dst[2 * XS] = ldv[i].z; dst[3 * XS] = ldv[i].w;
        }
    }

    for (int kt = 0; kt < 8; kt++) {
        __syncthreads();
        if (kt < 7) {
#pragma unroll
            for (int i = 0; i < 4; i++)
                ldv[i] = *reinterpret_cast<const float4*>(
                    X + (row0 + r_[i]) * 256 + (kt + 1) * KTILE + k4_[i] * 4);
        }
        const float* bx = sX + (kt & 1) * (KTILE * XS) + rp * 2;
        const float2* wbase = sW2 + (size_t)kt * KTILE * 32 + cg * 8;
#pragma unroll
        for (int kk = 0; kk < KTILE; kk++) {
            unsigned long long xp =
                *reinterpret_cast<const unsigned long long*>(bx + kk * XS);
            const ulonglong2* w2 =
                reinterpret_cast<const ulonglong2*>(wbase + kk * 32);
            ulonglong2 wa = w2[0], wb = w2[1], wc = w2[2], wd = w2[3];
            acc[0] = ffma2(wa.x, xp, acc[0]);
            acc[1] = ffma2(wa.y, xp, acc[1]);
            acc[2] = ffma2(wb.x, xp, acc[2]);
            acc[3] = ffma2(wb.y, xp, acc[3]);
            acc[4] = ffma2(wc.x, xp, acc[4]);
            acc[5] = ffma2(wc.y, xp, acc[5]);
            acc[6] = ffma2(wd.x, xp, acc[6]);
            acc[7] = ffma2(wd.y, xp, acc[7]);
        }
        if (kt < 7) {
            float* dstb = sX + ((kt + 1) & 1) * (KTILE * XS);
#pragma unroll
            for (int i = 0; i < 4; i++) {
                float* dst = dstb + k4_[i] * 4 * XS + r_[i];
                dst[0 * XS] = ldv[i].x; dst[1 * XS] = ldv[i].y;
                dst[2 * XS] = ldv[i].z; dst[3 * XS] = ldv[i].w;
            }
        }
    }

    // Epilogue: add bias + theta, write 2 rows x 8 cols.
    const float* bptr = (cg == 0) ? bf : (cg == 1) ? bi : (cg == 2) ? bg : bo;
    float o0[8], o1[8];
#pragma unroll
    for (int c = 0; c < 8; c++) {
        float bt = bptr[c] + th[cg * 8 + c];
        float2 av = *reinterpret_cast<float2*>(&acc[c]);
        o0[c] = av.x + bt;
        o1[c] = av.y + bt;
    }
    size_t r0 = row0 + (size_t)rp * 2;
    float4* p0 = reinterpret_cast<float4*>(g_pre + r0 * 32 + cg * 8);
    float4* p1 = reinterpret_cast<float4*>(g_pre + (r0 + 1) * 32 + cg * 8);
    p0[0] = make_float4(o0[0], o0[1], o0[2], o0[3]);
    p0[1] = make_float4(o0[4], o0[5], o0[6], o0[7]);
    p1[0] = make_float4(o1[0], o1[1], o1[2], o1[3]);
    p1[1] = make_float4(o1[4], o1[5], o1[6], o1[7]);
}

// ---------------------------------------------------------------------------
// Kernel 2: LSTM recurrence. One warp per batch element, lane = gate*8 + qubit.
// The quantum circuit is analytic:
//   m_k = prod_{j<=k} cos(ang_j)  (k>=1),   m_0 = prod_{j=1..7} cos(ang_j)
// ---------------------------------------------------------------------------
__global__ void __launch_bounds__(32) recur_kernel(
    const float* __restrict__ Wf, const float* __restrict__ Wi,
    const float* __restrict__ Wg, const float* __restrict__ Wo,
    float* __restrict__ out)
{
    const int b    = blockIdx.x;
    const int lane = threadIdx.x;
    const int g    = lane >> 3;
    const int n    = lane & 7;
    const unsigned FULL = 0xffffffffu;

    const float* Wsel = (g == 0) ? Wf : (g == 1) ? Wi : (g == 2) ? Wg : Wo;
    float wh[8];
#pragma unroll
    for (int h = 0; h < 8; h++) wh[h] = Wsel[n * 264 + 256 + h];

    float hxa[8];
#pragma unroll
    for (int h = 0; h < 8; h++) hxa[h] = 0.f;
    float cx = 0.f, hx = 0.f;

    const float* pb = g_pre + (size_t)b * 512 * 32 + lane;
    float* ob = out + (size_t)b * 512 * 8 + n;

    float pcur = pb[0];
    for (int t = 0; t < 512; t++) {
        float pnext = __ldg(pb + ((t + 1) & 511) * 32);  // prefetch (wrap unused)

        float ang = pcur;
#pragma unroll
        for (int h = 0; h < 8; h++) ang = fmaf(wh[h], hxa[h], ang);

        float c = __cosf(ang);

        // Inclusive prefix product over 8-lane segments (lanes 1..7 use this).
        float v = c, tmp;
        tmp = __shfl_up_sync(FULL, v, 1, 8); v *= (n >= 1) ? tmp : 1.f;
        tmp = __shfl_up_sync(FULL, v, 2, 8); v *= (n >= 2) ? tmp : 1.f;
        tmp = __shfl_up_sync(FULL, v, 4, 8); v *= (n >= 4) ? tmp : 1.f;
        // Full segment product with lane-0 value replaced by 1 (lane 0's m).
        float u = (n == 0) ? 1.f : c;
        tmp = __shfl_xor_sync(FULL, u, 1, 8); u *= tmp;
        tmp = __shfl_xor_sync(FULL, u, 2, 8); u *= tmp;
        tmp = __shfl_xor_sync(FULL, u, 4, 8); u *= tmp;
        float m = (n == 0) ? u : v;

        // Branchless activation: sigmoid for f,i,o; tanh(x)=2*sigmoid(2x)-1 for g.
        float xx = (g == 2) ? (m + m) : m;
        float sg = __fdividef(1.f, 1.f + __expf(-xx));
        float a  = (g == 2) ? (sg + sg - 1.f) : sg;

        // Gather all four gates for qubit n (every lane keeps its qubit's state).
        float fv = __shfl_sync(FULL, a, n);
        float iv = __shfl_sync(FULL, a, n + 8);
        float gv = __shfl_sync(FULL, a, n + 16);
        float ov = __shfl_sync(FULL, a, n + 24);

        cx = fmaf(fv, cx, iv * gv);
        float e  = __expf(-(cx + cx));
        float tc = __fdividef(2.f, 1.f + e) - 1.f;
        hx = ov * tc;

        // Broadcast full hx vector to every lane for the next step's matvec.
#pragma unroll
        for (int h = 0; h < 8; h++) hxa[h] = __shfl_sync(FULL, hx, h);

        if (lane < 8) ob[t * 8] = hx;
        pcur = pnext;
    }

    if (lane < 8) {
        out[2097152 + b * 8 + n] = hx;            // final hx
        out[2097152 + 4096 + b * 8 + n] = cx;     // final cx
    }
}

// ---------------------------------------------------------------------------
extern "C" void kernel_launch(void* const* d_in, const int* in_sizes, int n_in,
                              void* d_out, int out_size) {
    const float* X  = (const float*)d_in[0];
    const float* Wf = (const float*)d_in[1];
    const float* bf = (const float*)d_in[2];
    const float* Wi = (const float*)d_in[3];
    const float* bi = (const float*)d_in[4];
    const float* Wg = (const float*)d_in[5];
    const float* bg = (const float*)d_in[6];
    const float* Wo = (const float*)d_in[7];
    const float* bo = (const float*)d_in[8];
    const float* th = (const float*)d_in[9];
    float* out = (float*)d_out;

    const int smem = 16384 * sizeof(float) + 2 * KTILE * XS * sizeof(float); // 98816 B
    cudaFuncSetAttribute(gemm_kernel,
                         cudaFuncAttributeMaxDynamicSharedMemorySize, smem);

    gemm_kernel<<<2048, 256, smem>>>(X, Wf, bf, Wi, bi, Wg, bg, Wo, bo, th);
    recur_kernel<<<512, 32>>>(Wf, Wi, Wg, Wo, out);
}

// round 8
// speedup vs baseline: 1.4904x; 1.4904x over previous
#include <cuda_runtime.h>
#include <cstdint>

// Scratch: pre[row=b*512+t][32] (col = gate*8 + qubit). 33.5 MB (L2-resident).
__device__ float g_pre[512 * 512 * 32];

// ---------------------------------------------------------------------------
// Packed fp32x2 FMA: two fp32 MACs per issue slot, full fp32 precision.
// ---------------------------------------------------------------------------
__device__ __forceinline__ unsigned long long ffma2(unsigned long long a,
                                                    unsigned long long b,
                                                    unsigned long long c) {
    unsigned long long d;
    asm("fma.rn.f32x2 %0, %1, %2, %3;" : "=l"(d) : "l"(a), "l"(b), "l"(c));
    return d;
}
__device__ __forceinline__ float ex2_approx(float x) {
    float y; asm("ex2.approx.f32 %0, %1;" : "=f"(y) : "f"(x)); return y;
}
__device__ __forceinline__ float rcp_approx(float x) {
    float y; asm("rcp.approx.f32 %0, %1;" : "=f"(y) : "f"(x)); return y;
}

// ---------------------------------------------------------------------------
// Kernel 1: pre[r][c] = sum_k X[r][k]*W[c][k] + bias[c] + theta[c]
//   M=262144, K=256, N=32. Block: 256 thr, tile 256 rows x 32 cols.
//   Thread: 4 rows (2 packed pairs) x 8 cols -> 22 instrs / 32 MACs.
// ---------------------------------------------------------------------------
constexpr int KT  = 16;    // k-tile
constexpr int RB  = 256;   // rows per block
constexpr int XS2 = 258;   // padded smem row stride (floats)

__global__ void __launch_bounds__(256, 2) gemm_kernel(
    const float* __restrict__ X,
    const float* __restrict__ Wf, const float* __restrict__ bf,
    const float* __restrict__ Wi, const float* __restrict__ bi,
    const float* __restrict__ Wg, const float* __restrict__ bg,
    const float* __restrict__ Wo, const float* __restrict__ bo,
    const float* __restrict__ th)
{
    extern __shared__ float sm[];
    float2* sW2 = reinterpret_cast<float2*>(sm);   // [256][32] dup pairs, 64 KB
    float*  sX  = sm + 16384;                      // [2][KT][XS2], 33 KB

    const int tid = threadIdx.x;

    // Stage W as duplicated (w,w) pairs (row stride 264; first 256 = input part).
#pragma unroll
    for (int gi = 0; gi < 4; gi++) {
        const float* Wp = (gi == 0) ? Wf : (gi == 1) ? Wi : (gi == 2) ? Wg : Wo;
        for (int idx = tid; idx < 2048; idx += 256) {
            int k = idx >> 3, nn = idx & 7;
            float w = Wp[nn * 264 + k];
            sW2[k * 32 + gi * 8 + nn] = make_float2(w, w);
        }
    }

    const size_t row0 = (size_t)blockIdx.x * RB;
    const int rp = tid & 63;          // row-pair id: rows 2rp,2rp+1 and +128
    const int cg = tid >> 6;          // col group (gate), uniform per warp
    const int rq = tid >> 2;          // staging row base (0..63)
    const int k4 = tid & 3;           // staging k-chunk

    float4 ldv[4];
#pragma unroll
    for (int i = 0; i < 4; i++)
        ldv[i] = *reinterpret_cast<const float4*>(
            X + (row0 + rq + 64 * i) * 256 + k4 * 4);

    unsigned long long accA[8], accB[8];
#pragma unroll
    for (int c = 0; c < 8; c++) { accA[c] = 0ull; accB[c] = 0ull; }

    // store tile 0 into buffer 0
#pragma unroll
    for (int i = 0; i < 4; i++) {
        float* dst = sX + k4 * 4 * XS2 + rq + 64 * i;
        dst[0 * XS2] = ldv[i].x; dst[1 * XS2] = ldv[i].y;
        dst[2 * XS2] = ldv[i].z; dst[3 * XS2] = ldv[i].w;
    }

    for (int kt = 0; kt < 16; kt++) {
        __syncthreads();
        if (kt < 15) {
#pragma unroll
            for (int i = 0; i < 4; i++)
                ldv[i] = *reinterpret_cast<const float4*>(
                    X + (row0 + rq + 64 * i) * 256 + (kt + 1) * KT + k4 * 4);
        }
        const float*  bx = sX + (kt & 1) * (KT * XS2);
        const float2* wk = sW2 + (size_t)kt * KT * 32 + cg * 8;
#pragma unroll
        for (int kk = 0; kk < KT; kk++) {
            unsigned long long xA = *reinterpret_cast<const unsigned long long*>(
                bx + kk * XS2 + 2 * rp);
            unsigned long long xB = *reinterpret_cast<const unsigned long long*>(
                bx + kk * XS2 + 2 * rp + 128);
            const ulonglong2* w2 = reinterpret_cast<const ulonglong2*>(wk + kk * 32);
            ulonglong2 wa = w2[0], wb = w2[1], wc = w2[2], wd = w2[3];
            accA[0] = ffma2(wa.x, xA, accA[0]);  accB[0] = ffma2(wa.x, xB, accB[0]);
            accA[1] = ffma2(wa.y, xA, accA[1]);  accB[1] = ffma2(wa.y, xB, accB[1]);
            accA[2] = ffma2(wb.x, xA, accA[2]);  accB[2] = ffma2(wb.x, xB, accB[2]);
            accA[3] = ffma2(wb.y, xA, accA[3]);  accB[3] = ffma2(wb.y, xB, accB[3]);
            accA[4] = ffma2(wc.x, xA, accA[4]);  accB[4] = ffma2(wc.x, xB, accB[4]);
            accA[5] = ffma2(wc.y, xA, accA[5]);  accB[5] = ffma2(wc.y, xB, accB[5]);
            accA[6] = ffma2(wd.x, xA, accA[6]);  accB[6] = ffma2(wd.x, xB, accB[6]);
            accA[7] = ffma2(wd.y, xA, accA[7]);  accB[7] = ffma2(wd.y, xB, accB[7]);
        }
        if (kt < 15) {
            float* dstb = sX + ((kt + 1) & 1) * (KT * XS2);
#pragma unroll
            for (int i = 0; i < 4; i++) {
                float* dst = dstb + k4 * 4 * XS2 + rq + 64 * i;
                dst[0 * XS2] = ldv[i].x; dst[1 * XS2] = ldv[i].y;
                dst[2 * XS2] = ldv[i].z; dst[3 * XS2] = ldv[i].w;
            }
        }
    }

    // Epilogue
    const float* bptr = (cg == 0) ? bf : (cg == 1) ? bi : (cg == 2) ? bg : bo;
    float a0[8], a1[8], b0[8], b1[8];
#pragma unroll
    for (int c = 0; c < 8; c++) {
        float bt = bptr[c] + th[cg * 8 + c];
        float2 av = *reinterpret_cast<float2*>(&accA[c]);
        float2 bv = *reinterpret_cast<float2*>(&accB[c]);
        a0[c] = av.x + bt; a1[c] = av.y + bt;
        b0[c] = bv.x + bt; b1[c] = bv.y + bt;
    }
    size_t rr = row0 + (size_t)rp * 2;
    float4* pA0 = reinterpret_cast<float4*>(g_pre + rr * 32 + cg * 8);
    float4* pA1 = reinterpret_cast<float4*>(g_pre + (rr + 1) * 32 + cg * 8);
    float4* pB0 = reinterpret_cast<float4*>(g_pre + (rr + 128) * 32 + cg * 8);
    float4* pB1 = reinterpret_cast<float4*>(g_pre + (rr + 129) * 32 + cg * 8);
    pA0[0] = make_float4(a0[0], a0[1], a0[2], a0[3]);
    pA0[1] = make_float4(a0[4], a0[5], a0[6], a0[7]);
    pA1[0] = make_float4(a1[0], a1[1], a1[2], a1[3]);
    pA1[1] = make_float4(a1[4], a1[5], a1[6], a1[7]);
    pB0[0] = make_float4(b0[0], b0[1], b0[2], b0[3]);
    pB0[1] = make_float4(b0[4], b0[5], b0[6], b0[7]);
    pB1[0] = make_float4(b1[0], b1[1], b1[2], b1[3]);
    pB1[1] = make_float4(b1[4], b1[5], b1[6], b1[7]);
}

// ---------------------------------------------------------------------------
// Kernel 2: LSTM recurrence, one warp per batch, lane = gate*8 + qubit.
//   m_k = prod_{j<=k} cos(ang_j) (k>=1),  m_0 = prod_{j=1..7} cos(ang_j)
// Scan replaced by: broadcast 8 cosines (1 shuffle batch) + masked tree product.
// ---------------------------------------------------------------------------
__global__ void __launch_bounds__(32) recur_kernel(
    const float* __restrict__ Wf, const float* __restrict__ Wi,
    const float* __restrict__ Wg, const float* __restrict__ Wo,
    float* __restrict__ out)
{
    const int b    = blockIdx.x;
    const int lane = threadIdx.x;
    const int g    = lane >> 3;
    const int n    = lane & 7;
    const int segb = g * 8;
    const unsigned FULL = 0xffffffffu;
    const float L2E = 1.4426950408889634f;

    const float* Wsel = (g == 0) ? Wf : (g == 1) ? Wi : (g == 2) ? Wg : Wo;
    float wh[8];
#pragma unroll
    for (int h = 0; h < 8; h++) wh[h] = Wsel[n * 264 + 256 + h];

    // Inclusion mask for the product: n==0 -> j in 1..7, else j in 0..n.
    float incm[8];
#pragma unroll
    for (int j = 0; j < 8; j++)
        incm[j] = ((n == 0) ? (j >= 1) : (j <= n)) ? 1.0f : 0.0f;

    // Activation constants: gates f,i,o -> sigmoid; gate g -> tanh = 2*sig(2x)-1.
    const float sA2 = (g == 2) ? (-2.0f * L2E) : (-L2E);  // ex2 argument scale
    const float am  = (g == 2) ? 2.0f : 1.0f;
    const float ab  = (g == 2) ? -1.0f : 0.0f;

    float hxa[8];
#pragma unroll
    for (int h = 0; h < 8; h++) hxa[h] = 0.f;
    float cx = 0.f, hx = 0.f;

    const float* pb = g_pre + (size_t)b * 512 * 32 + lane;
    float* ob = out + (size_t)b * 512 * 8 + n;

    float p0 = pb[0];
    float p1 = __ldg(pb + 32);
    for (int t = 0; t < 512; t++) {
        float p2 = __ldg(pb + ((t + 2) & 511) * 32);  // distance-2 prefetch

        // angle = pre + W_h . hx  (two parallel fma chains)
        float s1 = p0, s2 = 0.f;
        s1 = fmaf(wh[0], hxa[0], s1);  s2 = fmaf(wh[1], hxa[1], s2);
        s1 = fmaf(wh[2], hxa[2], s1);  s2 = fmaf(wh[3], hxa[3], s2);
        s1 = fmaf(wh[4], hxa[4], s1);  s2 = fmaf(wh[5], hxa[5], s2);
        s1 = fmaf(wh[6], hxa[6], s1);  s2 = fmaf(wh[7], hxa[7], s2);
        float ang = s1 + s2;

        float cm1 = __cosf(ang) - 1.0f;

        // Broadcast (cos-1) of all 8 qubits in this gate segment (independent shuffles)
        float vv[8];
#pragma unroll
        for (int j = 0; j < 8; j++) {
            float cj = __shfl_sync(FULL, cm1, segb + j);
            vv[j] = fmaf(incm[j], cj, 1.0f);   // include -> cos, exclude -> 1
        }
        float m = ((vv[0] * vv[1]) * (vv[2] * vv[3])) *
                  ((vv[4] * vv[5]) * (vv[6] * vv[7]));

        // activation: r = sigmoid(scale*m); a = am*r + ab
        float e = ex2_approx(m * sA2);
        float r = rcp_approx(1.0f + e);
        float a = fmaf(am, r, ab);

        // gather the four gate activations for this lane's qubit
        float fv = __shfl_sync(FULL, a, n);
        float iv = __shfl_sync(FULL, a, n + 8);
        float gv = __shfl_sync(FULL, a, n + 16);
        float ov = __shfl_sync(FULL, a, n + 24);

        cx = fmaf(fv, cx, iv * gv);

        // hx = ov * tanh(cx);  tanh(x) = 2*sigmoid(2x)-1
        float e2 = ex2_approx(cx * (-2.0f * L2E));
        float r2 = rcp_approx(1.0f + e2);
        hx = ov * fmaf(2.0f, r2, -1.0f);

        // broadcast hx vector for next step's matvec
#pragma unroll
        for (int h = 0; h < 8; h++) hxa[h] = __shfl_sync(FULL, hx, h);

        if (lane < 8) ob[t * 8] = hx;
        p0 = p1; p1 = p2;
    }

    if (lane < 8) {
        out[2097152 + b * 8 + n] = hx;           // final hx
        out[2097152 + 4096 + b * 8 + n] = cx;    // final cx
    }
}

// ---------------------------------------------------------------------------
extern "C" void kernel_launch(void* const* d_in, const int* in_sizes, int n_in,
                              void* d_out, int out_size) {
    const float* X  = (const float*)d_in[0];
    const float* Wf = (const float*)d_in[1];
    const float* bf = (const float*)d_in[2];
    const float* Wi = (const float*)d_in[3];
    const float* bi = (const float*)d_in[4];
    const float* Wg = (const float*)d_in[5];
    const float* bg = (const float*)d_in[6];
    const float* Wo = (const float*)d_in[7];
    const float* bo = (const float*)d_in[8];
    const float* th = (const float*)d_in[9];
    float* out = (float*)d_out;

    const int smem = 16384 * 4 + 2 * KT * XS2 * 4;  // 98560 B
    cudaFuncSetAttribute(gemm_kernel,
                         cudaFuncAttributeMaxDynamicSharedMemorySize, smem);

    gemm_kernel<<<1024, 256, smem>>>(X, Wf, bf, Wi, bi, Wg, bg, Wo, bo, th);
    recur_kernel<<<512, 32>>>(Wf, Wi, Wg, Wo, out);
}